// round 11
// baseline (speedup 1.0000x reference)
#include <cuda_runtime.h>
#include <math.h>

// Problem dims
#define BB   64
#define TT   512
#define DIN  64
#define DM   512
#define DOUT 64

// 128 CTAs = 4 row-blocks x 32 col-blocks, 512 threads each.
#define NCTA 128
#define NTHR 512
#define RB   16   // batch rows per CTA
#define CB   16   // h columns per CTA
#define AST  20   // h-activation smem row stride (floats, 80B: 16B-aligned)
#define XST  16   // x-activation smem row stride (64B rows: aligned + conflict-free)
#define WST  16   // weight smem row stride
#define RS   18   // reduction array output-row stride

// Transposed ping-pong hidden state in global: [k][batch-row], L2-resident,
// accessed .cg only.
__device__ float g_h0T[2][DM * BB];
__device__ float g_h1T[2][DM * BB];
// Transposed input: g_xT[t][k][row] (written once in a prepass).
__device__ float g_xT[TT * DIN * BB];
// Epoch-parity barrier flags, scoped per row-block group (32 CTAs).
__device__ unsigned g_flags[2][4][32];

struct __align__(16) Smem {
    float  sAT[DM][AST];      // h0(t), transposed [k][row]
    float  sBT[DM][AST];      // h1(t-1), transposed
    float  sXT[DIN][XST];     // x(t+1) tile, transposed
    float  whh0T[DM][WST];    // weight col-slices [k][col]
    float  wih1T[DM][WST];
    float  whh1T[DM][WST];
    float  wih0T[DIN][WST];
    float2 woutT[DM];         // 2 output columns of Wout
    float  redB[16][CB * RS]; // layer-1 k-group partials
    float  redA[16][CB * RS]; // layer-0 k-group partials
    float2 redo[16][17];      // out-GEMM partials [kgroup][row]
    float  cb0[CB], cb1[CB];
    float2 cbo;
};

// ---- L2-direct (L1-bypass) accessors for the exchanged hidden state ----
__device__ __forceinline__ void ldcg4(const float *p, float4 &v) {
    asm volatile("ld.global.cg.v4.f32 {%0,%1,%2,%3}, [%4];"
                 : "=f"(v.x), "=f"(v.y), "=f"(v.z), "=f"(v.w)
                 : "l"(p));
}
__device__ __forceinline__ void stcg(float *p, float v) {
    asm volatile("st.global.cg.f32 [%0], %1;" ::"l"(p), "f"(v));
}

// ---- barrier primitives: CG-style release/acquire, no CCTL.IVALL ----
__device__ __forceinline__ void flag_arrive(unsigned e, int rb, int cb) {
    asm volatile("st.release.gpu.u32 [%0], %1;" ::"l"(&g_flags[e & 1u][rb][cb]),
                 "r"(e)
                 : "memory");
}
__device__ __forceinline__ void flag_wait(unsigned e, int rb, int lane) {
    unsigned v;
    do {  // 32 consecutive u32 flags -> one coalesced 128B L2 probe per round
        asm volatile("ld.acquire.gpu.u32 %0, [%1];"
                     : "=r"(v)
                     : "l"(&g_flags[e & 1u][rb][lane])
                     : "memory");
    } while (!__all_sync(0xffffffffu, v == e));
}

// ---- packed f32x2 helpers (Blackwell FFMA2) ----
__device__ __forceinline__ unsigned long long pack2(float lo, float hi) {
    unsigned long long r;
    asm("mov.b64 %0, {%1, %2};" : "=l"(r) : "f"(lo), "f"(hi));
    return r;
}
__device__ __forceinline__ void unpack2(unsigned long long v, float &lo, float &hi) {
    asm("mov.b64 {%0, %1}, %2;" : "=f"(lo), "=f"(hi) : "l"(v));
}
__device__ __forceinline__ void fma2(unsigned long long &d, unsigned long long a,
                                     unsigned long long b) {
    asm("fma.rn.f32x2 %0, %1, %2, %0;" : "+l"(d) : "l"(a), "l"(b));
}
__device__ __forceinline__ unsigned long long add2(unsigned long long a,
                                                   unsigned long long b) {
    unsigned long long r;
    asm("add.rn.f32x2 %0, %1, %2;" : "=l"(r) : "l"(a), "l"(b));
    return r;
}

// 4-row x 4-col tile, 32-way k-split (ks = 2*warp + lane-half): per k-iter one
// a LDS.128 (4 rows) + one/two w LDS.128 whose 64-bit halves are direct f32x2
// operands. 48B of LDS per 64 fused MACs.
template <int NI, int ASTR, bool FUSE>
__device__ __forceinline__ void gemm44(const float *__restrict__ aT,
                                       const float *__restrict__ w1T,
                                       const float *__restrict__ w2T, int ks,
                                       int r4, int c4,
                                       unsigned long long accB[4][2],
                                       unsigned long long accA[4][2]) {
#pragma unroll 4
    for (int i = 0; i < NI; i++) {
        int k = i * 32 + ks;
        float4 a = *(const float4 *)&aT[k * ASTR + r4];
        ulonglong2 w1 = *(const ulonglong2 *)&w1T[k * WST + c4];
        unsigned long long a0 = pack2(a.x, a.x);
        unsigned long long a1 = pack2(a.y, a.y);
        unsigned long long a2 = pack2(a.z, a.z);
        unsigned long long a3 = pack2(a.w, a.w);
        fma2(accB[0][0], a0, w1.x);
        fma2(accB[0][1], a0, w1.y);
        fma2(accB[1][0], a1, w1.x);
        fma2(accB[1][1], a1, w1.y);
        fma2(accB[2][0], a2, w1.x);
        fma2(accB[2][1], a2, w1.y);
        fma2(accB[3][0], a3, w1.x);
        fma2(accB[3][1], a3, w1.y);
        if (FUSE) {
            ulonglong2 w2 = *(const ulonglong2 *)&w2T[k * WST + c4];
            fma2(accA[0][0], a0, w2.x);
            fma2(accA[0][1], a0, w2.y);
            fma2(accA[1][0], a1, w2.x);
            fma2(accA[1][1], a1, w2.y);
            fma2(accA[2][0], a2, w2.x);
            fma2(accA[2][1], a2, w2.y);
            fma2(accA[3][0], a3, w2.x);
            fma2(accA[3][1], a3, w2.y);
        }
    }
}

// Pair-shuffle reduce (lanes l and l^16 hold k-groups 2w and 2w+1 for the same
// tile position), then scatter: lo lanes store rows r4+0..1, hi lanes r4+2..3.
__device__ __forceinline__ void pairReduceScatter(float (*__restrict__ red)[CB * RS],
                                                  unsigned long long acc[4][2],
                                                  int wid, int hiHalf, int r4,
                                                  int c4) {
    int keep = hiHalf ? 2 : 0;  // rows this lane keeps
    int send = hiHalf ? 0 : 2;  // rows this lane sends to partner
#pragma unroll
    for (int rr = 0; rr < 2; rr++) {
#pragma unroll
        for (int cp = 0; cp < 2; cp++) {
            unsigned long long got =
                __shfl_xor_sync(0xffffffffu, acc[send + rr][cp], 16);
            unsigned long long tot = add2(acc[keep + rr][cp], got);
            float x, y;
            unpack2(tot, x, y);
            *(float2 *)&red[wid][(r4 + keep + rr) * RS + c4 + 2 * cp] =
                make_float2(x, y);
        }
    }
}

// Final reduce: red reads conflict-free (orr*18+oc distinct banks); stores to
// transposed global h coalesced.
__device__ __forceinline__ void finalReduceH(const float (*__restrict__ red)[CB * RS],
                                             const float *__restrict__ cb,
                                             float *__restrict__ gdstT, int o, int r0,
                                             int c0) {
    int orr = o & 15, oc = o >> 4;
    float s = cb[oc];
#pragma unroll
    for (int j = 0; j < 16; j++) s += red[j][orr * RS + oc];
    stcg(&gdstT[(c0 + oc) * BB + r0 + orr], tanhf(s));
}

// Staging from transposed global h: 4 x (LDG.128.cg + STS.128) per thread.
__device__ __forceinline__ void stageH(float (*__restrict__ dst)[AST],
                                       const float *__restrict__ srcT, int r0,
                                       int tid) {
#pragma unroll
    for (int it = 0; it < 4; it++) {
        int task = it * NTHR + tid;  // 0..2047
        int k = task >> 2, rg = (task & 3) << 2;
        float4 v;
        ldcg4(&srcT[k * BB + r0 + rg], v);
        *(float4 *)&dst[k][rg] = v;
    }
}

// x staging from pre-transposed g_xT (threads 0..255). XST=16 -> rows are
// 64B apart: float4 stores aligned.
__device__ __forceinline__ void stageX(Smem &S, int r0, int tx, int tid) {
    if (tid < 256) {
        int k = tid >> 2, rg = (tid & 3) << 2;
        float4 v = *(const float4 *)&g_xT[((size_t)tx * DIN + k) * BB + r0 + rg];
        *(float4 *)&S.sXT[k][rg] = v;
    }
}

// out-GEMM: every lane computes the packed 2-col dot for row (lane&15) over its
// k-split, pair-shuffles with lane^16, lo lanes store redo[warp][row].
__device__ __forceinline__ void out_partial(Smem &S, int wid, int lane, int ks) {
    int row = lane & 15;
    unsigned long long o0 = pack2(0.f, 0.f), o1 = pack2(0.f, 0.f);
#pragma unroll 8
    for (int i = 0; i < 16; i += 2) {
        int k0 = i * 32 + ks, k1 = (i + 1) * 32 + ks;
        float a0v = S.sBT[k0][row], a1v = S.sBT[k1][row];
        unsigned long long w0 = *(const unsigned long long *)&S.woutT[k0];
        unsigned long long w1 = *(const unsigned long long *)&S.woutT[k1];
        fma2(o0, pack2(a0v, a0v), w0);
        fma2(o1, pack2(a1v, a1v), w1);
    }
    unsigned long long tot = add2(o0, o1);
    tot = add2(tot, __shfl_xor_sync(0xffffffffu, tot, 16));
    if (lane < 16) {
        float x, y;
        unpack2(tot, x, y);
        S.redo[wid][row] = make_float2(x, y);
    }
}

__global__ void __launch_bounds__(NTHR, 1)
rnn_persistent_kernel(const float *__restrict__ data, const float *__restrict__ Wih0,
                      const float *__restrict__ bih0, const float *__restrict__ Whh0,
                      const float *__restrict__ bhh0, const float *__restrict__ Wih1,
                      const float *__restrict__ bih1, const float *__restrict__ Whh1,
                      const float *__restrict__ bhh1, const float *__restrict__ Wout,
                      const float *__restrict__ bout, float *__restrict__ out) {
    extern __shared__ char smem_raw[];
    Smem &S = *reinterpret_cast<Smem *>(smem_raw);

    const int tid = threadIdx.x;
    const int cta = blockIdx.x;
    const int rb = cta >> 5;   // 0..3
    const int cb = cta & 31;   // 0..31
    const int r0 = rb * RB;
    const int c0 = cb * CB;
    const int oc0 = cb * 2;
    // GEMM mapping: 16 warps; ks = 2*warp + lane-half (32-way k-split);
    // 16 tile positions of 4x4 covering the 16x16 output.
    const int wid = tid >> 5;
    const int lane = tid & 31;
    const int hiHalf = lane >> 4;
    const int ks = (wid << 1) | hiHalf;
    const int pos = lane & 15;
    const int r4 = ((pos >> 2) & 3) << 2;
    const int c4 = (pos & 3) << 2;

    // ---- one-time: weights -> smem ----
    for (int idx = tid; idx < DM * 16; idx += NTHR) {
        int k = idx >> 4, c = idx & 15;
        S.whh0T[k][c] = Whh0[k * DM + c0 + c];
        S.wih1T[k][c] = Wih1[k * DM + c0 + c];
        S.whh1T[k][c] = Whh1[k * DM + c0 + c];
    }
    for (int idx = tid; idx < DIN * 16; idx += NTHR) {
        int k = idx >> 4, c = idx & 15;
        S.wih0T[k][c] = Wih0[k * DM + c0 + c];
    }
    for (int k = tid; k < DM; k += NTHR)
        S.woutT[k] = *(const float2 *)&Wout[k * DOUT + oc0];
    if (tid < CB) {
        S.cb0[tid] = bih0[c0 + tid] + bhh0[c0 + tid];
        S.cb1[tid] = bih1[c0 + tid] + bhh1[c0 + tid];
    }
    if (tid == 0) S.cbo = make_float2(bout[oc0], bout[oc0 + 1]);

    // ---- prepass: transpose this CTA's share of x into g_xT ----
#pragma unroll
    for (int it = 0; it < 8; it++) {
        int task = it * NTHR + tid;  // 0..4095
        int tt = cb * 16 + (task >> 8);
        int k = (task >> 2) & 63;
        int rg = (task & 3) << 2;
        float4 v;
        v.x = data[((size_t)(r0 + rg + 0) * TT + tt) * DIN + k];
        v.y = data[((size_t)(r0 + rg + 1) * TT + tt) * DIN + k];
        v.z = data[((size_t)(r0 + rg + 2) * TT + tt) * DIN + k];
        v.w = data[((size_t)(r0 + rg + 3) * TT + tt) * DIN + k];
        *(float4 *)&g_xT[((size_t)tt * DIN + k) * BB + r0 + rg] = v;
    }

    unsigned epoch = 1;  // x(all t) visible within row group
    __syncthreads();
    if (tid == 0) flag_arrive(epoch, rb, cb);
    if (tid < 32) flag_wait(epoch, rb, tid);
    __syncthreads();

    // ---- prologue: h0(0) = tanh(x(0) @ Wih0 + b0) ----
    stageX(S, r0, 0, tid);
    __syncthreads();
    {
        unsigned long long accA[4][2], dummy[4][2];
#pragma unroll
        for (int i = 0; i < 4; i++) accA[i][0] = accA[i][1] = pack2(0.f, 0.f);
        gemm44<2, XST, false>(&S.sXT[0][0], &S.wih0T[0][0], nullptr, ks, r4, c4,
                              accA, dummy);
        pairReduceScatter(S.redA, accA, wid, hiHalf, r4, c4);
    }
    __syncthreads();
    if (tid >= 256) finalReduceH(S.redA, S.cb0, g_h0T[0], tid - 256, r0, c0);

    epoch++;
    __syncthreads();
    if (tid == 0) flag_arrive(epoch, rb, cb);
    if (tid < 32) flag_wait(epoch, rb, tid);
    __syncthreads();

#pragma unroll 1
    for (int t = 0; t < TT; t++) {
        // Buffers: h0(t) in g_h0T[t&1]; h1(t-1) in g_h1T[(t+1)&1].
        // This iteration writes h1(t) -> g_h1T[t&1], h0(t+1) -> g_h0T[(t+1)&1].
        stageH(S.sAT, g_h0T[t & 1], r0, tid);
        if (t > 0) stageH(S.sBT, g_h1T[(t + 1) & 1], r0, tid);
        stageX(S, r0, (t < TT - 1) ? t + 1 : TT - 1, tid);
        __syncthreads();

        unsigned long long accB[4][2], accA[4][2];
#pragma unroll
        for (int i = 0; i < 4; i++) {
            accB[i][0] = accB[i][1] = pack2(0.f, 0.f);
            accA[i][0] = accA[i][1] = pack2(0.f, 0.f);
        }

        // Fused over sAT: accB += sAT@Wih1, accA += sAT@Whh0 (shared a-loads)
        gemm44<16, AST, true>(&S.sAT[0][0], &S.wih1T[0][0], &S.whh0T[0][0], ks, r4,
                              c4, accB, accA);
        // accA += x(t+1)@Wih0
        {
            unsigned long long dummy[4][2];
            gemm44<2, XST, false>(&S.sXT[0][0], &S.wih0T[0][0], nullptr, ks, r4, c4,
                                  accA, dummy);
        }
        // accB += h1(t-1)@Whh1
        if (t > 0) {
            unsigned long long dummy[4][2];
            gemm44<16, AST, false>(&S.sBT[0][0], &S.whh1T[0][0], nullptr, ks, r4,
                                   c4, accB, dummy);
        }
        pairReduceScatter(S.redB, accB, wid, hiHalf, r4, c4);
        pairReduceScatter(S.redA, accA, wid, hiHalf, r4, c4);
        // out(t-1) partials from h1(t-1) (in sBT)
        if (t > 0) out_partial(S, wid, lane, ks);
        __syncthreads();

        // split final reduces: half threads layer-1, half layer-0
        if (tid < 256) {
            finalReduceH(S.redB, S.cb1, g_h1T[t & 1], tid, r0, c0);
        } else {
            finalReduceH(S.redA, S.cb0, g_h0T[(t + 1) & 1], tid - 256, r0, c0);
        }

        // barrier; out(t-1) final reduce hidden between arrive and wait
        epoch++;
        __syncthreads();
        if (tid == 0) flag_arrive(epoch, rb, cb);
        if (tid < 32) {
            if (t > 0 && tid < 16) {
                float s0 = S.cbo.x, s1 = S.cbo.y;
#pragma unroll
                for (int j = 0; j < 16; j++) {
                    float2 p = S.redo[j][tid];
                    s0 += p.x;
                    s1 += p.y;
                }
                *(float2 *)&out[((r0 + tid) * TT + (t - 1)) * DOUT + oc0] =
                    make_float2(s0, s1);
            }
            flag_wait(epoch, rb, tid);
        }
        __syncthreads();
    }

    // ---- epilogue: out(T-1) from h1(T-1) in g_h1T[1] ----
    stageH(S.sBT, g_h1T[1], r0, tid);
    __syncthreads();
    out_partial(S, wid, lane, ks);
    __syncthreads();
    if (tid < 16) {
        float s0 = S.cbo.x, s1 = S.cbo.y;
#pragma unroll
        for (int j = 0; j < 16; j++) {
            float2 p = S.redo[j][tid];
            s0 += p.x;
            s1 += p.y;
        }
        *(float2 *)&out[((r0 + tid) * TT + (TT - 1)) * DOUT + oc0] =
            make_float2(s0, s1);
    }
}

extern "C" void kernel_launch(void *const *d_in, const int *in_sizes, int n_in,
                              void *d_out, int out_size) {
    const float *data = (const float *)d_in[0];
    const float *Wih0 = (const float *)d_in[1];
    const float *bih0 = (const float *)d_in[2];
    const float *Whh0 = (const float *)d_in[3];
    const float *bhh0 = (const float *)d_in[4];
    const float *Wih1 = (const float *)d_in[5];
    const float *bih1 = (const float *)d_in[6];
    const float *Whh1 = (const float *)d_in[7];
    const float *bhh1 = (const float *)d_in[8];
    const float *Wout = (const float *)d_in[9];
    const float *bout = (const float *)d_in[10];
    float *out = (float *)d_out;

    cudaFuncSetAttribute(rnn_persistent_kernel,
                         cudaFuncAttributeMaxDynamicSharedMemorySize,
                         (int)sizeof(Smem));

    rnn_persistent_kernel<<<NCTA, NTHR, sizeof(Smem)>>>(
        data, Wih0, bih0, Whh0, bhh0, Wih1, bih1, Whh1, bhh1, Wout, bout, out);
}

// round 12
// speedup vs baseline: 1.0439x; 1.0439x over previous
#include <cuda_runtime.h>
#include <math.h>

// Problem dims
#define BB   64
#define TT   512
#define DIN  64
#define DM   512
#define DOUT 64

// 128 CTAs = 4 row-blocks x 32 col-blocks, 512 threads each.
#define NCTA 128
#define NTHR 512
#define RB   16   // batch rows per CTA
#define CB   16   // h columns per CTA
#define AST  16   // h-activation smem row stride: 64B rows -> the 4x4 a-load
                  // (rows 2w,2w+1 x 4 float4s) is one aligned 128B line/phase
#define XST  16   // x-activation smem row stride (64B rows)
#define WST  16   // weight smem row stride
#define RS   18   // reduction array output-row stride

// Transposed ping-pong hidden state in global: [k][batch-row], L2-resident,
// accessed .cg only.
__device__ float g_h0T[2][DM * BB];
__device__ float g_h1T[2][DM * BB];
// Transposed input: g_xT[t][k][row] (written once in a prepass).
__device__ float g_xT[TT * DIN * BB];
// Epoch-parity barrier flags, scoped per row-block group (32 CTAs).
__device__ unsigned g_flags[2][4][32];

struct __align__(16) Smem {
    float  sAT[DM][AST];      // h0(t), transposed [k][row]
    float  sBT[DM][AST];      // h1(t-1), transposed
    float  sXT[DIN][XST];     // x(t+1) tile, transposed
    float  whh0T[DM][WST];    // weight col-slices [k][col]
    float  wih1T[DM][WST];
    float  whh1T[DM][WST];
    float  wih0T[DIN][WST];
    float2 woutT[DM];         // 2 output columns of Wout
    float  redB[16][CB * RS]; // layer-1 k-group partials
    float  redA[16][CB * RS]; // layer-0 k-group partials
    float2 redo[16][17];      // out-GEMM partials [kgroup][row]
    float  cb0[CB], cb1[CB];
    float2 cbo;
};

// ---- L2-direct (L1-bypass) accessors for the exchanged hidden state ----
__device__ __forceinline__ void ldcg4(const float *p, float4 &v) {
    asm volatile("ld.global.cg.v4.f32 {%0,%1,%2,%3}, [%4];"
                 : "=f"(v.x), "=f"(v.y), "=f"(v.z), "=f"(v.w)
                 : "l"(p));
}
__device__ __forceinline__ void stcg(float *p, float v) {
    asm volatile("st.global.cg.f32 [%0], %1;" ::"l"(p), "f"(v));
}

// ---- barrier primitives: CG-style release/acquire, no CCTL.IVALL ----
__device__ __forceinline__ void flag_arrive(unsigned e, int rb, int cb) {
    asm volatile("st.release.gpu.u32 [%0], %1;" ::"l"(&g_flags[e & 1u][rb][cb]),
                 "r"(e)
                 : "memory");
}
__device__ __forceinline__ void flag_wait(unsigned e, int rb, int lane) {
    unsigned v;
    do {  // 32 consecutive u32 flags -> one coalesced 128B L2 probe per round
        asm volatile("ld.acquire.gpu.u32 %0, [%1];"
                     : "=r"(v)
                     : "l"(&g_flags[e & 1u][rb][lane])
                     : "memory");
    } while (!__all_sync(0xffffffffu, v == e));
}

// ---- packed f32x2 helpers (Blackwell FFMA2) ----
__device__ __forceinline__ unsigned long long pack2(float lo, float hi) {
    unsigned long long r;
    asm("mov.b64 %0, {%1, %2};" : "=l"(r) : "f"(lo), "f"(hi));
    return r;
}
__device__ __forceinline__ void unpack2(unsigned long long v, float &lo, float &hi) {
    asm("mov.b64 {%0, %1}, %2;" : "=f"(lo), "=f"(hi) : "l"(v));
}
__device__ __forceinline__ void fma2(unsigned long long &d, unsigned long long a,
                                     unsigned long long b) {
    asm("fma.rn.f32x2 %0, %1, %2, %0;" : "+l"(d) : "l"(a), "l"(b));
}
__device__ __forceinline__ unsigned long long add2(unsigned long long a,
                                                   unsigned long long b) {
    unsigned long long r;
    asm("add.rn.f32x2 %0, %1, %2;" : "=l"(r) : "l"(a), "l"(b));
    return r;
}

// 4-row x 4-col tile, 32-way k-split (ks = 2*warp + lane-half): per k-iter one
// a LDS.128 (4 rows) + one/two w LDS.128 whose 64-bit halves are direct f32x2
// operands. With AST=WST=16, each warp's a/w loads are exactly one 128B line.
template <int NI, int ASTR, bool FUSE>
__device__ __forceinline__ void gemm44(const float *__restrict__ aT,
                                       const float *__restrict__ w1T,
                                       const float *__restrict__ w2T, int ks,
                                       int r4, int c4,
                                       unsigned long long accB[4][2],
                                       unsigned long long accA[4][2]) {
#pragma unroll 4
    for (int i = 0; i < NI; i++) {
        int k = i * 32 + ks;
        float4 a = *(const float4 *)&aT[k * ASTR + r4];
        ulonglong2 w1 = *(const ulonglong2 *)&w1T[k * WST + c4];
        unsigned long long a0 = pack2(a.x, a.x);
        unsigned long long a1 = pack2(a.y, a.y);
        unsigned long long a2 = pack2(a.z, a.z);
        unsigned long long a3 = pack2(a.w, a.w);
        fma2(accB[0][0], a0, w1.x);
        fma2(accB[0][1], a0, w1.y);
        fma2(accB[1][0], a1, w1.x);
        fma2(accB[1][1], a1, w1.y);
        fma2(accB[2][0], a2, w1.x);
        fma2(accB[2][1], a2, w1.y);
        fma2(accB[3][0], a3, w1.x);
        fma2(accB[3][1], a3, w1.y);
        if (FUSE) {
            ulonglong2 w2 = *(const ulonglong2 *)&w2T[k * WST + c4];
            fma2(accA[0][0], a0, w2.x);
            fma2(accA[0][1], a0, w2.y);
            fma2(accA[1][0], a1, w2.x);
            fma2(accA[1][1], a1, w2.y);
            fma2(accA[2][0], a2, w2.x);
            fma2(accA[2][1], a2, w2.y);
            fma2(accA[3][0], a3, w2.x);
            fma2(accA[3][1], a3, w2.y);
        }
    }
}

// Pair-shuffle reduce (lanes l and l^16 hold k-groups 2w and 2w+1 for the same
// tile position), then scatter: lo lanes store rows r4+0..1, hi lanes r4+2..3.
__device__ __forceinline__ void pairReduceScatter(float (*__restrict__ red)[CB * RS],
                                                  unsigned long long acc[4][2],
                                                  int wid, int hiHalf, int r4,
                                                  int c4) {
    int keep = hiHalf ? 2 : 0;  // rows this lane keeps
    int send = hiHalf ? 0 : 2;  // rows this lane sends to partner
#pragma unroll
    for (int rr = 0; rr < 2; rr++) {
#pragma unroll
        for (int cp = 0; cp < 2; cp++) {
            unsigned long long got =
                __shfl_xor_sync(0xffffffffu, acc[send + rr][cp], 16);
            unsigned long long tot = add2(acc[keep + rr][cp], got);
            float x, y;
            unpack2(tot, x, y);
            *(float2 *)&red[wid][(r4 + keep + rr) * RS + c4 + 2 * cp] =
                make_float2(x, y);
        }
    }
}

// Final reduce: red reads conflict-free (orr*18+oc distinct banks); stores to
// transposed global h coalesced.
__device__ __forceinline__ void finalReduceH(const float (*__restrict__ red)[CB * RS],
                                             const float *__restrict__ cb,
                                             float *__restrict__ gdstT, int o, int r0,
                                             int c0) {
    int orr = o & 15, oc = o >> 4;
    float s = cb[oc];
#pragma unroll
    for (int j = 0; j < 16; j++) s += red[j][orr * RS + oc];
    stcg(&gdstT[(c0 + oc) * BB + r0 + orr], tanhf(s));
}

// Staging from transposed global h: 4 x (LDG.128.cg + STS.128) per thread.
// With AST=16, each warp's stores cover 512B contiguous -> 4 phases (optimal).
__device__ __forceinline__ void stageH(float (*__restrict__ dst)[AST],
                                       const float *__restrict__ srcT, int r0,
                                       int tid) {
#pragma unroll
    for (int it = 0; it < 4; it++) {
        int task = it * NTHR + tid;  // 0..2047
        int k = task >> 2, rg = (task & 3) << 2;
        float4 v;
        ldcg4(&srcT[k * BB + r0 + rg], v);
        *(float4 *)&dst[k][rg] = v;
    }
}

// x staging from pre-transposed g_xT (threads 0..255). XST=16 -> 64B rows,
// float4 stores aligned.
__device__ __forceinline__ void stageX(Smem &S, int r0, int tx, int tid) {
    if (tid < 256) {
        int k = tid >> 2, rg = (tid & 3) << 2;
        float4 v = *(const float4 *)&g_xT[((size_t)tx * DIN + k) * BB + r0 + rg];
        *(float4 *)&S.sXT[k][rg] = v;
    }
}

// out-GEMM: every lane computes the packed 2-col dot for row (lane&15) over its
// k-split, pair-shuffles with lane^16, lo lanes store redo[warp][row].
__device__ __forceinline__ void out_partial(Smem &S, int wid, int lane, int ks) {
    int row = lane & 15;
    unsigned long long o0 = pack2(0.f, 0.f), o1 = pack2(0.f, 0.f);
#pragma unroll 8
    for (int i = 0; i < 16; i += 2) {
        int k0 = i * 32 + ks, k1 = (i + 1) * 32 + ks;
        float a0v = S.sBT[k0][row], a1v = S.sBT[k1][row];
        unsigned long long w0 = *(const unsigned long long *)&S.woutT[k0];
        unsigned long long w1 = *(const unsigned long long *)&S.woutT[k1];
        fma2(o0, pack2(a0v, a0v), w0);
        fma2(o1, pack2(a1v, a1v), w1);
    }
    unsigned long long tot = add2(o0, o1);
    tot = add2(tot, __shfl_xor_sync(0xffffffffu, tot, 16));
    if (lane < 16) {
        float x, y;
        unpack2(tot, x, y);
        S.redo[wid][row] = make_float2(x, y);
    }
}

__global__ void __launch_bounds__(NTHR, 1)
rnn_persistent_kernel(const float *__restrict__ data, const float *__restrict__ Wih0,
                      const float *__restrict__ bih0, const float *__restrict__ Whh0,
                      const float *__restrict__ bhh0, const float *__restrict__ Wih1,
                      const float *__restrict__ bih1, const float *__restrict__ Whh1,
                      const float *__restrict__ bhh1, const float *__restrict__ Wout,
                      const float *__restrict__ bout, float *__restrict__ out) {
    extern __shared__ char smem_raw[];
    Smem &S = *reinterpret_cast<Smem *>(smem_raw);

    const int tid = threadIdx.x;
    const int cta = blockIdx.x;
    const int rb = cta >> 5;   // 0..3
    const int cb = cta & 31;   // 0..31
    const int r0 = rb * RB;
    const int c0 = cb * CB;
    const int oc0 = cb * 2;
    // GEMM mapping: 16 warps; ks = 2*warp + lane-half (32-way k-split);
    // 16 tile positions of 4x4 covering the 16x16 output.
    const int wid = tid >> 5;
    const int lane = tid & 31;
    const int hiHalf = lane >> 4;
    const int ks = (wid << 1) | hiHalf;
    const int pos = lane & 15;
    const int r4 = ((pos >> 2) & 3) << 2;
    const int c4 = (pos & 3) << 2;

    // ---- one-time: weights -> smem ----
    for (int idx = tid; idx < DM * 16; idx += NTHR) {
        int k = idx >> 4, c = idx & 15;
        S.whh0T[k][c] = Whh0[k * DM + c0 + c];
        S.wih1T[k][c] = Wih1[k * DM + c0 + c];
        S.whh1T[k][c] = Whh1[k * DM + c0 + c];
    }
    for (int idx = tid; idx < DIN * 16; idx += NTHR) {
        int k = idx >> 4, c = idx & 15;
        S.wih0T[k][c] = Wih0[k * DM + c0 + c];
    }
    for (int k = tid; k < DM; k += NTHR)
        S.woutT[k] = *(const float2 *)&Wout[k * DOUT + oc0];
    if (tid < CB) {
        S.cb0[tid] = bih0[c0 + tid] + bhh0[c0 + tid];
        S.cb1[tid] = bih1[c0 + tid] + bhh1[c0 + tid];
    }
    if (tid == 0) S.cbo = make_float2(bout[oc0], bout[oc0 + 1]);

    // ---- prepass: transpose this CTA's share of x into g_xT ----
#pragma unroll
    for (int it = 0; it < 8; it++) {
        int task = it * NTHR + tid;  // 0..4095
        int tt = cb * 16 + (task >> 8);
        int k = (task >> 2) & 63;
        int rg = (task & 3) << 2;
        float4 v;
        v.x = data[((size_t)(r0 + rg + 0) * TT + tt) * DIN + k];
        v.y = data[((size_t)(r0 + rg + 1) * TT + tt) * DIN + k];
        v.z = data[((size_t)(r0 + rg + 2) * TT + tt) * DIN + k];
        v.w = data[((size_t)(r0 + rg + 3) * TT + tt) * DIN + k];
        *(float4 *)&g_xT[((size_t)tt * DIN + k) * BB + r0 + rg] = v;
    }

    unsigned epoch = 1;  // x(all t) visible within row group
    __syncthreads();
    if (tid == 0) flag_arrive(epoch, rb, cb);
    if (tid < 32) flag_wait(epoch, rb, tid);
    __syncthreads();

    // ---- prologue: h0(0) = tanh(x(0) @ Wih0 + b0) ----
    stageX(S, r0, 0, tid);
    __syncthreads();
    {
        unsigned long long accA[4][2], dummy[4][2];
#pragma unroll
        for (int i = 0; i < 4; i++) accA[i][0] = accA[i][1] = pack2(0.f, 0.f);
        gemm44<2, XST, false>(&S.sXT[0][0], &S.wih0T[0][0], nullptr, ks, r4, c4,
                              accA, dummy);
        pairReduceScatter(S.redA, accA, wid, hiHalf, r4, c4);
    }
    __syncthreads();
    if (tid >= 256) finalReduceH(S.redA, S.cb0, g_h0T[0], tid - 256, r0, c0);

    epoch++;
    __syncthreads();
    if (tid == 0) flag_arrive(epoch, rb, cb);
    if (tid < 32) flag_wait(epoch, rb, tid);
    __syncthreads();

#pragma unroll 1
    for (int t = 0; t < TT; t++) {
        // Buffers: h0(t) in g_h0T[t&1]; h1(t-1) in g_h1T[(t+1)&1].
        // This iteration writes h1(t) -> g_h1T[t&1], h0(t+1) -> g_h0T[(t+1)&1].
        stageH(S.sAT, g_h0T[t & 1], r0, tid);
        if (t > 0) stageH(S.sBT, g_h1T[(t + 1) & 1], r0, tid);
        stageX(S, r0, (t < TT - 1) ? t + 1 : TT - 1, tid);
        __syncthreads();

        unsigned long long accB[4][2], accA[4][2];
#pragma unroll
        for (int i = 0; i < 4; i++) {
            accB[i][0] = accB[i][1] = pack2(0.f, 0.f);
            accA[i][0] = accA[i][1] = pack2(0.f, 0.f);
        }

        // Fused over sAT: accB += sAT@Wih1, accA += sAT@Whh0 (shared a-loads)
        gemm44<16, AST, true>(&S.sAT[0][0], &S.wih1T[0][0], &S.whh0T[0][0], ks, r4,
                              c4, accB, accA);
        // accA += x(t+1)@Wih0
        {
            unsigned long long dummy[4][2];
            gemm44<2, XST, false>(&S.sXT[0][0], &S.wih0T[0][0], nullptr, ks, r4, c4,
                                  accA, dummy);
        }
        // accB += h1(t-1)@Whh1
        if (t > 0) {
            unsigned long long dummy[4][2];
            gemm44<16, AST, false>(&S.sBT[0][0], &S.whh1T[0][0], nullptr, ks, r4,
                                   c4, accB, dummy);
        }
        pairReduceScatter(S.redB, accB, wid, hiHalf, r4, c4);
        pairReduceScatter(S.redA, accA, wid, hiHalf, r4, c4);
        // out(t-1) partials from h1(t-1) (in sBT)
        if (t > 0) out_partial(S, wid, lane, ks);
        __syncthreads();

        // split final reduces: half threads layer-1, half layer-0
        if (tid < 256) {
            finalReduceH(S.redB, S.cb1, g_h1T[t & 1], tid, r0, c0);
        } else {
            finalReduceH(S.redA, S.cb0, g_h0T[(t + 1) & 1], tid - 256, r0, c0);
        }

        // barrier; out(t-1) final reduce hidden between arrive and wait
        epoch++;
        __syncthreads();
        if (tid == 0) flag_arrive(epoch, rb, cb);
        if (tid < 32) {
            if (t > 0 && tid < 16) {
                float s0 = S.cbo.x, s1 = S.cbo.y;
#pragma unroll
                for (int j = 0; j < 16; j++) {
                    float2 p = S.redo[j][tid];
                    s0 += p.x;
                    s1 += p.y;
                }
                *(float2 *)&out[((r0 + tid) * TT + (t - 1)) * DOUT + oc0] =
                    make_float2(s0, s1);
            }
            flag_wait(epoch, rb, tid);
        }
        __syncthreads();
    }

    // ---- epilogue: out(T-1) from h1(T-1) in g_h1T[1] ----
    stageH(S.sBT, g_h1T[1], r0, tid);
    __syncthreads();
    out_partial(S, wid, lane, ks);
    __syncthreads();
    if (tid < 16) {
        float s0 = S.cbo.x, s1 = S.cbo.y;
#pragma unroll
        for (int j = 0; j < 16; j++) {
            float2 p = S.redo[j][tid];
            s0 += p.x;
            s1 += p.y;
        }
        *(float2 *)&out[((r0 + tid) * TT + (TT - 1)) * DOUT + oc0] =
            make_float2(s0, s1);
    }
}

extern "C" void kernel_launch(void *const *d_in, const int *in_sizes, int n_in,
                              void *d_out, int out_size) {
    const float *data = (const float *)d_in[0];
    const float *Wih0 = (const float *)d_in[1];
    const float *bih0 = (const float *)d_in[2];
    const float *Whh0 = (const float *)d_in[3];
    const float *bhh0 = (const float *)d_in[4];
    const float *Wih1 = (const float *)d_in[5];
    const float *bih1 = (const float *)d_in[6];
    const float *Whh1 = (const float *)d_in[7];
    const float *bhh1 = (const float *)d_in[8];
    const float *Wout = (const float *)d_in[9];
    const float *bout = (const float *)d_in[10];
    float *out = (float *)d_out;

    cudaFuncSetAttribute(rnn_persistent_kernel,
                         cudaFuncAttributeMaxDynamicSharedMemorySize,
                         (int)sizeof(Smem));

    rnn_persistent_kernel<<<NCTA, NTHR, sizeof(Smem)>>>(
        data, Wih0, bih0, Whh0, bhh0, Wih1, bih1, Whh1, bhh1, Wout, bout, out);
}

// round 14
// speedup vs baseline: 1.1233x; 1.0761x over previous
#include <cuda_runtime.h>
#include <math.h>

// Problem dims
#define BB   64
#define TT   512
#define DIN  64
#define DM   512
#define DOUT 64

// 128 CTAs = 4 row-blocks x 32 col-blocks, 1024 threads each (32 warps).
#define NCTA 128
#define NTHR 1024
#define RB   16   // batch rows per CTA
#define CB   16   // h columns per CTA
#define AST  16   // h-activation smem row stride (64B rows, aligned, 4-phase STS)
#define XST  16   // x-activation smem row stride
#define WST  16   // weight smem row stride
#define RS   18   // reduction array output-row stride

// Transposed ping-pong hidden state in global: [k][batch-row], L2-resident,
// accessed .cg only.
__device__ float g_h0T[2][DM * BB];
__device__ float g_h1T[2][DM * BB];
// Transposed input: g_xT[t][k][row] (written once in a prepass).
__device__ float g_xT[TT * DIN * BB];
// Epoch-parity barrier flags, scoped per row-block group (32 CTAs).
__device__ unsigned g_flags[2][4][32];

struct __align__(16) Smem {
    float  sAT[DM][AST];      // h0(t), transposed [k][row]
    float  sBT[DM][AST];      // h1(t-1), transposed
    float  sXT[DIN][XST];     // x(t+1) tile, transposed
    float  whh0T[DM][WST];    // weight col-slices [k][col]
    float  wih1T[DM][WST];
    float  whh1T[DM][WST];
    float  wih0T[DIN][WST];
    float2 woutT[DM];         // 2 output columns of Wout
    float  redB[16][CB * RS]; // layer-1 partials (32 k-groups pair-merged to 16)
    float  redA[16][CB * RS]; // layer-0 partials
    float2 redo[32][17];      // out-GEMM partials [kgroup][row]
    float  cb0[CB], cb1[CB];
    float2 cbo;
};

// ---- L2-direct (L1-bypass) accessors for the exchanged hidden state ----
__device__ __forceinline__ void ldcg4(const float *p, float4 &v) {
    asm volatile("ld.global.cg.v4.f32 {%0,%1,%2,%3}, [%4];"
                 : "=f"(v.x), "=f"(v.y), "=f"(v.z), "=f"(v.w)
                 : "l"(p));
}
__device__ __forceinline__ void stcg(float *p, float v) {
    asm volatile("st.global.cg.f32 [%0], %1;" ::"l"(p), "f"(v));
}

// ---- barrier primitives: CG-style release/acquire, no CCTL.IVALL ----
__device__ __forceinline__ void flag_arrive(unsigned e, int rb, int cb) {
    asm volatile("st.release.gpu.u32 [%0], %1;" ::"l"(&g_flags[e & 1u][rb][cb]),
                 "r"(e)
                 : "memory");
}
__device__ __forceinline__ void flag_wait(unsigned e, int rb, int lane) {
    unsigned v;
    do {  // 32 consecutive u32 flags -> one coalesced 128B L2 probe per round
        asm volatile("ld.acquire.gpu.u32 %0, [%1];"
                     : "=r"(v)
                     : "l"(&g_flags[e & 1u][rb][lane])
                     : "memory");
    } while (!__all_sync(0xffffffffu, v == e));
}

// ---- packed f32x2 helpers (Blackwell FFMA2) ----
__device__ __forceinline__ unsigned long long pack2(float lo, float hi) {
    unsigned long long r;
    asm("mov.b64 %0, {%1, %2};" : "=l"(r) : "f"(lo), "f"(hi));
    return r;
}
__device__ __forceinline__ void unpack2(unsigned long long v, float &lo, float &hi) {
    asm("mov.b64 {%0, %1}, %2;" : "=f"(lo), "=f"(hi) : "l"(v));
}
__device__ __forceinline__ void fma2(unsigned long long &d, unsigned long long a,
                                     unsigned long long b) {
    asm("fma.rn.f32x2 %0, %1, %2, %0;" : "+l"(d) : "l"(a), "l"(b));
}
__device__ __forceinline__ unsigned long long add2(unsigned long long a,
                                                   unsigned long long b) {
    unsigned long long r;
    asm("add.rn.f32x2 %0, %1, %2;" : "=l"(r) : "l"(a), "l"(b));
    return r;
}

// 2-row x 4-col tile, 32-way k-split with ks = warp id: every smem access has
// warp-uniform k (w LDS.128 = 4-address broadcast, a LDS.64 covers all 32
// banks exactly once). Weight LDS.128 halves are direct f32x2 operands.
template <int NI, int ASTR, bool FUSE>
__device__ __forceinline__ void gemm_rc(const float *__restrict__ aT,
                                        const float *__restrict__ w1T,
                                        const float *__restrict__ w2T, int ks,
                                        int r2, int c4,
                                        unsigned long long accB[2][2],
                                        unsigned long long accA[2][2]) {
#pragma unroll 2
    for (int i = 0; i < NI; i++) {
        int k = i * 32 + ks;
        unsigned long long av = *(const unsigned long long *)&aT[k * ASTR + r2];
        ulonglong2 w1 = *(const ulonglong2 *)&w1T[k * WST + c4];
        float ax, ay;
        unpack2(av, ax, ay);
        unsigned long long a0 = pack2(ax, ax);
        unsigned long long a1 = pack2(ay, ay);
        fma2(accB[0][0], a0, w1.x);
        fma2(accB[0][1], a0, w1.y);
        fma2(accB[1][0], a1, w1.x);
        fma2(accB[1][1], a1, w1.y);
        if (FUSE) {
            ulonglong2 w2 = *(const ulonglong2 *)&w2T[k * WST + c4];
            fma2(accA[0][0], a0, w2.x);
            fma2(accA[0][1], a0, w2.y);
            fma2(accA[1][0], a1, w2.x);
            fma2(accA[1][1], a1, w2.y);
        }
    }
}

// Warps 0-15: write partials.
__device__ __forceinline__ void scatter(float (*__restrict__ red)[CB * RS],
                                        unsigned long long acc[2][2], int slot,
                                        int r2, int c4) {
#pragma unroll
    for (int r = 0; r < 2; r++)
#pragma unroll
        for (int cp = 0; cp < 2; cp++) {
            float x, y;
            unpack2(acc[r][cp], x, y);
            *(float2 *)&red[slot][(r2 + r) * RS + c4 + 2 * cp] = make_float2(x, y);
        }
}

// Warps 16-31: merge-add their k-group into the matching slot (same cell is
// touched by exactly one thread, so plain read-add-write is race-free).
__device__ __forceinline__ void mergeAdd(float (*__restrict__ red)[CB * RS],
                                         unsigned long long acc[2][2], int slot,
                                         int r2, int c4) {
#pragma unroll
    for (int r = 0; r < 2; r++)
#pragma unroll
        for (int cp = 0; cp < 2; cp++) {
            unsigned long long *p =
                (unsigned long long *)&red[slot][(r2 + r) * RS + c4 + 2 * cp];
            *p = add2(*p, acc[r][cp]);
        }
}

// Final reduce: red reads conflict-free; stores to transposed global h
// coalesced (each warp writes 2 contiguous 64B rows of g_hT).
__device__ __forceinline__ void finalReduceH(const float (*__restrict__ red)[CB * RS],
                                             const float *__restrict__ cb,
                                             float *__restrict__ gdstT, int o, int r0,
                                             int c0) {
    int orr = o & 15, oc = o >> 4;
    float s = cb[oc];
#pragma unroll
    for (int j = 0; j < 16; j++) s += red[j][orr * RS + oc];
    stcg(&gdstT[(c0 + oc) * BB + r0 + orr], tanhf(s));
}

// Staging from transposed global h: 2 x (LDG.128.cg + STS.128) per thread.
__device__ __forceinline__ void stageH(float (*__restrict__ dst)[AST],
                                       const float *__restrict__ srcT, int r0,
                                       int tid) {
#pragma unroll
    for (int it = 0; it < 2; it++) {
        int task = it * NTHR + tid;  // 0..2047
        int k = task >> 2, rg = (task & 3) << 2;
        float4 v;
        ldcg4(&srcT[k * BB + r0 + rg], v);
        *(float4 *)&dst[k][rg] = v;
    }
}

// x staging from pre-transposed g_xT (threads 0..255).
__device__ __forceinline__ void stageX(Smem &S, int r0, int tx, int tid) {
    if (tid < 256) {
        int k = tid >> 2, rg = (tid & 3) << 2;
        float4 v = *(const float4 *)&g_xT[((size_t)tx * DIN + k) * BB + r0 + rg];
        *(float4 *)&S.sXT[k][rg] = v;
    }
}

// out-GEMM: lane halves split k further (k = (2i+half)*32 + wid), pair-shuffle
// merges, lo lanes store redo[wid][row].
__device__ __forceinline__ void out_partial(Smem &S, int wid, int lane) {
    int row = lane & 15;
    int half = lane >> 4;
    unsigned long long o0 = pack2(0.f, 0.f), o1 = pack2(0.f, 0.f);
#pragma unroll
    for (int i = 0; i < 8; i++) {
        int k = (2 * i + half) * 32 + wid;
        float av = S.sBT[k][row];
        unsigned long long w = *(const unsigned long long *)&S.woutT[k];
        fma2((i & 1) ? o1 : o0, pack2(av, av), w);
    }
    unsigned long long tot = add2(o0, o1);
    tot = add2(tot, __shfl_xor_sync(0xffffffffu, tot, 16));
    if (lane < 16) {
        float x, y;
        unpack2(tot, x, y);
        S.redo[wid][row] = make_float2(x, y);
    }
}

__global__ void __launch_bounds__(NTHR, 1)
rnn_persistent_kernel(const float *__restrict__ data, const float *__restrict__ Wih0,
                      const float *__restrict__ bih0, const float *__restrict__ Whh0,
                      const float *__restrict__ bhh0, const float *__restrict__ Wih1,
                      const float *__restrict__ bih1, const float *__restrict__ Whh1,
                      const float *__restrict__ bhh1, const float *__restrict__ Wout,
                      const float *__restrict__ bout, float *__restrict__ out) {
    extern __shared__ char smem_raw[];
    Smem &S = *reinterpret_cast<Smem *>(smem_raw);

    const int tid = threadIdx.x;
    const int cta = blockIdx.x;
    const int rb = cta >> 5;   // 0..3
    const int cb = cta & 31;   // 0..31
    const int r0 = rb * RB;
    const int c0 = cb * CB;
    const int oc0 = cb * 2;
    // GEMM mapping: 32 warps; ks = wid (32-way k-split, warp-uniform);
    // 32 tile positions of 2r x 4c covering the 16x16 output.
    const int wid = tid >> 5;
    const int lane = tid & 31;
    const int ks = wid;
    const int slot = wid & 15;       // reduction slot (pair-merged)
    const bool writer = (wid < 16);  // scatter vs merge role
    const int r2 = (lane >> 2) * 2;
    const int c4 = (lane & 3) * 4;

    // ---- one-time: weights -> smem ----
    for (int idx = tid; idx < DM * 16; idx += NTHR) {
        int k = idx >> 4, c = idx & 15;
        S.whh0T[k][c] = Whh0[k * DM + c0 + c];
        S.wih1T[k][c] = Wih1[k * DM + c0 + c];
        S.whh1T[k][c] = Whh1[k * DM + c0 + c];
    }
    if (tid < DIN * 16) {
        int k = tid >> 4, c = tid & 15;
        S.wih0T[k][c] = Wih0[k * DM + c0 + c];
    }
    for (int k = tid; k < DM; k += NTHR)
        S.woutT[k] = *(const float2 *)&Wout[k * DOUT + oc0];
    if (tid < CB) {
        S.cb0[tid] = bih0[c0 + tid] + bhh0[c0 + tid];
        S.cb1[tid] = bih1[c0 + tid] + bhh1[c0 + tid];
    }
    if (tid == 0) S.cbo = make_float2(bout[oc0], bout[oc0 + 1]);

    // ---- prepass: transpose this CTA's share of x into g_xT ----
#pragma unroll
    for (int it = 0; it < 4; it++) {
        int task = it * NTHR + tid;  // 0..4095
        int tt = cb * 16 + (task >> 8);
        int k = (task >> 2) & 63;
        int rg = (task & 3) << 2;
        float4 v;
        v.x = data[((size_t)(r0 + rg + 0) * TT + tt) * DIN + k];
        v.y = data[((size_t)(r0 + rg + 1) * TT + tt) * DIN + k];
        v.z = data[((size_t)(r0 + rg + 2) * TT + tt) * DIN + k];
        v.w = data[((size_t)(r0 + rg + 3) * TT + tt) * DIN + k];
        *(float4 *)&g_xT[((size_t)tt * DIN + k) * BB + r0 + rg] = v;
    }

    unsigned epoch = 1;  // x(all t) visible within row group
    __syncthreads();
    if (tid == 0) flag_arrive(epoch, rb, cb);
    if (tid < 32) flag_wait(epoch, rb, tid);
    __syncthreads();

    // ---- prologue: h0(0) = tanh(x(0) @ Wih0 + b0) ----
    stageX(S, r0, 0, tid);
    __syncthreads();
    {
        unsigned long long accA[2][2], dummy[2][2];
        accA[0][0] = accA[0][1] = accA[1][0] = accA[1][1] = pack2(0.f, 0.f);
        gemm_rc<2, XST, false>(&S.sXT[0][0], &S.wih0T[0][0], nullptr, ks, r2, c4,
                               accA, dummy);
        if (writer) scatter(S.redA, accA, slot, r2, c4);
        __syncthreads();
        if (!writer) mergeAdd(S.redA, accA, slot, r2, c4);
    }
    __syncthreads();
    if (tid >= 256 && tid < 512)
        finalReduceH(S.redA, S.cb0, g_h0T[0], tid - 256, r0, c0);

    epoch++;
    __syncthreads();
    if (tid == 0) flag_arrive(epoch, rb, cb);
    if (tid < 32) flag_wait(epoch, rb, tid);
    __syncthreads();

#pragma unroll 1
    for (int t = 0; t < TT; t++) {
        // Buffers: h0(t) in g_h0T[t&1]; h1(t-1) in g_h1T[(t+1)&1].
        // This iteration writes h1(t) -> g_h1T[t&1], h0(t+1) -> g_h0T[(t+1)&1].
        stageH(S.sAT, g_h0T[t & 1], r0, tid);
        if (t > 0) stageH(S.sBT, g_h1T[(t + 1) & 1], r0, tid);
        stageX(S, r0, (t < TT - 1) ? t + 1 : TT - 1, tid);
        __syncthreads();

        unsigned long long accB[2][2], accA[2][2];
        accB[0][0] = accB[0][1] = accB[1][0] = accB[1][1] = pack2(0.f, 0.f);
        accA[0][0] = accA[0][1] = accA[1][0] = accA[1][1] = pack2(0.f, 0.f);

        // Fused over sAT: accB += sAT@Wih1, accA += sAT@Whh0 (shared a-loads)
        gemm_rc<16, AST, true>(&S.sAT[0][0], &S.wih1T[0][0], &S.whh0T[0][0], ks, r2,
                               c4, accB, accA);
        // accA += x(t+1)@Wih0
        {
            unsigned long long dummy[2][2];
            gemm_rc<2, XST, false>(&S.sXT[0][0], &S.wih0T[0][0], nullptr, ks, r2, c4,
                                   accA, dummy);
        }
        // accB += h1(t-1)@Whh1
        if (t > 0) {
            unsigned long long dummy[2][2];
            gemm_rc<16, AST, false>(&S.sBT[0][0], &S.whh1T[0][0], nullptr, ks, r2,
                                    c4, accB, dummy);
        }
        // out(t-1) partials from h1(t-1) (in sBT)
        if (t > 0) out_partial(S, wid, lane);

        // two-round k-reduction: scatter (warps 0-15) then merge (16-31)
        if (writer) {
            scatter(S.redB, accB, slot, r2, c4);
            scatter(S.redA, accA, slot, r2, c4);
        }
        __syncthreads();
        if (!writer) {
            mergeAdd(S.redB, accB, slot, r2, c4);
            mergeAdd(S.redA, accA, slot, r2, c4);
        }
        __syncthreads();

        // final reduces: threads 0-255 layer-1, 256-511 layer-0
        if (tid < 256) {
            finalReduceH(S.redB, S.cb1, g_h1T[t & 1], tid, r0, c0);
        } else if (tid < 512) {
            finalReduceH(S.redA, S.cb0, g_h0T[(t + 1) & 1], tid - 256, r0, c0);
        }

        // barrier; out(t-1) final reduce hidden between arrive and wait
        epoch++;
        __syncthreads();
        if (tid == 0) flag_arrive(epoch, rb, cb);
        if (tid < 32) {
            if (t > 0 && tid < 16) {
                float s0 = S.cbo.x, s1 = S.cbo.y;
#pragma unroll
                for (int j = 0; j < 32; j++) {
                    float2 p = S.redo[j][tid];
                    s0 += p.x;
                    s1 += p.y;
                }
                *(float2 *)&out[((r0 + tid) * TT + (t - 1)) * DOUT + oc0] =
                    make_float2(s0, s1);
            }
            flag_wait(epoch, rb, tid);
        }
        __syncthreads();
    }

    // ---- epilogue: out(T-1) from h1(T-1) in g_h1T[1] ----
    stageH(S.sBT, g_h1T[1], r0, tid);
    __syncthreads();
    out_partial(S, wid, lane);
    __syncthreads();
    if (tid < 16) {
        float s0 = S.cbo.x, s1 = S.cbo.y;
#pragma unroll
        for (int j = 0; j < 32; j++) {
            float2 p = S.redo[j][tid];
            s0 += p.x;
            s1 += p.y;
        }
        *(float2 *)&out[((r0 + tid) * TT + (TT - 1)) * DOUT + oc0] =
            make_float2(s0, s1);
    }
}

extern "C" void kernel_launch(void *const *d_in, const int *in_sizes, int n_in,
                              void *d_out, int out_size) {
    const float *data = (const float *)d_in[0];
    const float *Wih0 = (const float *)d_in[1];
    const float *bih0 = (const float *)d_in[2];
    const float *Whh0 = (const float *)d_in[3];
    const float *bhh0 = (const float *)d_in[4];
    const float *Wih1 = (const float *)d_in[5];
    const float *bih1 = (const float *)d_in[6];
    const float *Whh1 = (const float *)d_in[7];
    const float *bhh1 = (const float *)d_in[8];
    const float *Wout = (const float *)d_in[9];
    const float *bout = (const float *)d_in[10];
    float *out = (float *)d_out;

    cudaFuncSetAttribute(rnn_persistent_kernel,
                         cudaFuncAttributeMaxDynamicSharedMemorySize,
                         (int)sizeof(Smem));

    rnn_persistent_kernel<<<NCTA, NTHR, sizeof(Smem)>>>(
        data, Wih0, bih0, Whh0, bhh0, Wih1, bih1, Whh1, bhh1, Wout, bout, out);
}